// round 4
// baseline (speedup 1.0000x reference)
#include <cuda_runtime.h>
#include <cuda_bf16.h>
#include <cstdint>

// Repara_PhC: permittivity = sigmoid((Z - 0.5)/T), Z = Fx^T * Fy (rank-96 separable).
// Stage 1: precompute Fx, Fy (96 x 4001 padded to 4096, zero-padded tails).
// Stage 2: 128x128-tile GEMM, 256 threads, 8x8 microtile, packed FFMA2 (fma.rn.f32x2),
//          fused sigmoid epilogue. K processed in 2 chunks of 48 (static smem 48KB).
// R3 fix: Bs128 row stride is 32 ulonglong2 (128 floats), not 16.

#define GN    4001
#define KH    96
#define PITCH 4096
#define TILE  128
#define KC    48

__device__ float g_Fx[KH * PITCH];
__device__ float g_Fy[KH * PITCH];

__global__ void precompute_factors(const float* __restrict__ holes) {
    int i = blockIdx.x * blockDim.x + threadIdx.x;   // 0..PITCH-1
    int h = blockIdx.y;                               // 0..95
    int which = blockIdx.z;                           // 0 = Fx, 1 = Fy
    if (i >= PITCH) return;
    float c = holes[h * 3 + (which ? 1 : 0)];
    float s = holes[h * 3 + 2];
    float inv2s2 = 1.0f / (2.0f * s * s);
    float v = 0.0f;
    if (i < GN) {
        float g = -10.0f + 0.005f * (float)i;
        float d = g - c;
        v = __expf(-d * d * inv2s2);
    }
    if (which == 0) g_Fx[h * PITCH + i] = v;
    else            g_Fy[h * PITCH + i] = v;
}

#define DUP(d, f)      asm("mov.b64 %0, {%1, %1};" : "=l"(d) : "r"(__float_as_uint(f)))
#define FMA2(acc, a, b) asm("fma.rn.f32x2 %0, %1, %2, %3;" : "=l"(acc) : "l"(a), "l"(b), "l"(acc))

__global__ __launch_bounds__(256, 2) void gemm_sigmoid(const float* __restrict__ Tptr,
                                                       float* __restrict__ out) {
    __shared__ float As[KC][TILE];   // Fx chunk: [k][i_local]
    __shared__ float Bs[KC][TILE];   // Fy chunk: [k][j_local]

    const int i0 = blockIdx.y * TILE;
    const int j0 = blockIdx.x * TILE;
    const int tid = threadIdx.x;
    const int tx = tid & 15;        // 16 groups of 8 j
    const int ty = tid >> 4;        // 16 groups of 8 i

    uint64_t acc[8][4];
    #pragma unroll
    for (int ii = 0; ii < 8; ++ii)
        #pragma unroll
        for (int jj = 0; jj < 4; ++jj) acc[ii][jj] = 0ull;

    float4* As4 = (float4*)&As[0][0];                  // 32 float4 per k-row
    const ulonglong2* Bs128 = (const ulonglong2*)&Bs[0][0];  // 32 ulonglong2 per k-row

    for (int c = 0; c < 2; ++c) {
        // Cooperative load: KC*TILE floats = 1536 float4 per operand, 6 per thread.
        #pragma unroll
        for (int l = 0; l < 6; ++l) {
            int idx = tid + l * 256;
            int k = idx >> 5;          // / 32
            int v = idx & 31;          // float4 within row
            ((float4*)As)[idx] = *(const float4*)&g_Fx[(c * KC + k) * PITCH + i0 + v * 4];
            ((float4*)Bs)[idx] = *(const float4*)&g_Fy[(c * KC + k) * PITCH + j0 + v * 4];
        }
        __syncthreads();

        #pragma unroll 4
        for (int k = 0; k < KC; ++k) {
            float4 a0 = As4[k * 32 + ty * 2];
            float4 a1 = As4[k * 32 + ty * 2 + 1];
            ulonglong2 bb0 = Bs128[k * 32 + tx * 2];       // FIX: stride 32
            ulonglong2 bb1 = Bs128[k * 32 + tx * 2 + 1];   // FIX: stride 32
            uint64_t bv0 = bb0.x, bv1 = bb0.y, bv2 = bb1.x, bv3 = bb1.y;

            uint64_t ad0, ad1, ad2, ad3, ad4, ad5, ad6, ad7;
            DUP(ad0, a0.x); DUP(ad1, a0.y); DUP(ad2, a0.z); DUP(ad3, a0.w);
            DUP(ad4, a1.x); DUP(ad5, a1.y); DUP(ad6, a1.z); DUP(ad7, a1.w);

            FMA2(acc[0][0], ad0, bv0); FMA2(acc[0][1], ad0, bv1);
            FMA2(acc[0][2], ad0, bv2); FMA2(acc[0][3], ad0, bv3);
            FMA2(acc[1][0], ad1, bv0); FMA2(acc[1][1], ad1, bv1);
            FMA2(acc[1][2], ad1, bv2); FMA2(acc[1][3], ad1, bv3);
            FMA2(acc[2][0], ad2, bv0); FMA2(acc[2][1], ad2, bv1);
            FMA2(acc[2][2], ad2, bv2); FMA2(acc[2][3], ad2, bv3);
            FMA2(acc[3][0], ad3, bv0); FMA2(acc[3][1], ad3, bv1);
            FMA2(acc[3][2], ad3, bv2); FMA2(acc[3][3], ad3, bv3);
            FMA2(acc[4][0], ad4, bv0); FMA2(acc[4][1], ad4, bv1);
            FMA2(acc[4][2], ad4, bv2); FMA2(acc[4][3], ad4, bv3);
            FMA2(acc[5][0], ad5, bv0); FMA2(acc[5][1], ad5, bv1);
            FMA2(acc[5][2], ad5, bv2); FMA2(acc[5][3], ad5, bv3);
            FMA2(acc[6][0], ad6, bv0); FMA2(acc[6][1], ad6, bv1);
            FMA2(acc[6][2], ad6, bv2); FMA2(acc[6][3], ad6, bv3);
            FMA2(acc[7][0], ad7, bv0); FMA2(acc[7][1], ad7, bv1);
            FMA2(acc[7][2], ad7, bv2); FMA2(acc[7][3], ad7, bv3);
        }
        __syncthreads();
    }

    const float invT = __fdividef(1.0f, *Tptr);
    const int jb = j0 + tx * 8;

    #pragma unroll
    for (int ii = 0; ii < 8; ++ii) {
        int i = i0 + ty * 8 + ii;
        if (i >= GN) continue;
        size_t rowbase = (size_t)i * GN;
        #pragma unroll
        for (int jp = 0; jp < 4; ++jp) {
            uint64_t p = acc[ii][jp];
            float lo = __uint_as_float((uint32_t)p);
            float hi = __uint_as_float((uint32_t)(p >> 32));
            int j = jb + jp * 2;
            if (j < GN) {
                float z = (lo - 0.5f) * invT;
                out[rowbase + j] = __fdividef(1.0f, 1.0f + __expf(-z));
            }
            if (j + 1 < GN) {
                float z = (hi - 0.5f) * invT;
                out[rowbase + j + 1] = __fdividef(1.0f, 1.0f + __expf(-z));
            }
        }
    }
}

extern "C" void kernel_launch(void* const* d_in, const int* in_sizes, int n_in,
                              void* d_out, int out_size) {
    const float* holes = (const float*)d_in[0];   // 96 x (x0,y0,sigma)
    const float* Tptr  = (const float*)d_in[1];
    float* out = (float*)d_out;                   // 4001 x 4001 fp32

    {
        dim3 grid((PITCH + 255) / 256, KH, 2);
        precompute_factors<<<grid, 256>>>(holes);
    }
    {
        dim3 grid((GN + TILE - 1) / TILE, (GN + TILE - 1) / TILE);  // 32 x 32
        gemm_sigmoid<<<grid, 256>>>(Tptr, out);
    }
}

// round 6
// speedup vs baseline: 3.5303x; 3.5303x over previous
#include <cuda_runtime.h>
#include <cstdint>
#include <cstddef>

// Repara_PhC via sparsity: each Gaussian (sigma=0.1) dies below 1e-7 beyond
// r ~ 0.57 units. Kernel A builds a per-64x64px-tile list of contributing
// holes (rect-distance cutoff 2*s^2*ln(1e7)); Kernel B evaluates only those
// holes per pixel (avg ~0.5 exp/px instead of 96 FMA/px) + fused sigmoid.
// Lists are built with order-preserving ballot compaction -> deterministic
// summation order -> bitwise-deterministic output.

#define GN     4001
#define NT     63          // 63 tiles of 64 px cover 4032 >= 4001
#define TPX    64
#define MAXH   32
#define NHOLES 192
#define LOG2E  1.442695041f

__device__ int g_cnt[NT * NT];
__device__ int g_list[NT * NT][MAXH];

// ---------- Kernel A: per-tile hole lists (one block per tile, 192 threads) ----------
__global__ void build_lists(const float* __restrict__ holes) {
    const int t  = blockIdx.x;
    const int ti = t / NT, tj = t % NT;
    const float xlo = -10.f + 0.005f * (float)(ti * TPX);
    const float xhi = -10.f + 0.005f * (float)(ti * TPX + TPX - 1);
    const float ylo = -10.f + 0.005f * (float)(tj * TPX);
    const float yhi = -10.f + 0.005f * (float)(tj * TPX + TPX - 1);

    const int h = threadIdx.x;            // hole index, 0..191
    const float cx = holes[3 * h];
    const float cy = holes[3 * h + 1];
    const float s  = holes[3 * h + 2];
    const float dx = fmaxf(fmaxf(xlo - cx, cx - xhi), 0.f);
    const float dy = fmaxf(fmaxf(ylo - cy, cy - yhi), 0.f);
    // keep hole if exp(-d^2/(2 s^2)) >= ~1e-7  <=>  d^2 <= 2 s^2 * ln(1e7)
    const bool in = (dx * dx + dy * dy) <= (2.f * s * s * 16.2f);

    __shared__ int wcnt[6], woff[6];
    const unsigned m = __ballot_sync(0xffffffffu, in);
    const int w = h >> 5;
    if ((h & 31) == 0) wcnt[w] = __popc(m);
    __syncthreads();
    if (h == 0) {
        int o = 0;
        #pragma unroll
        for (int i = 0; i < 6; ++i) { woff[i] = o; o += wcnt[i]; }
        g_cnt[t] = o < MAXH ? o : MAXH;
    }
    __syncthreads();
    if (in) {
        int pos = woff[w] + __popc(m & ((1u << (h & 31)) - 1u));
        if (pos < MAXH) g_list[t][pos] = h;   // ascending hole order: deterministic
    }
}

// ---------- Kernel B: evaluate tile ----------
__device__ __forceinline__ float ex2f(float x) {
    float r; asm("ex2.approx.ftz.f32 %0, %1;" : "=f"(r) : "f"(x)); return r;
}
__device__ __forceinline__ float rcpf(float x) {
    float r; asm("rcp.approx.ftz.f32 %0, %1;" : "=f"(r) : "f"(x)); return r;
}

__global__ __launch_bounds__(256) void eval_tiles(const float* __restrict__ holes,
                                                  const float* __restrict__ Tptr,
                                                  float* __restrict__ out) {
    const int ti = blockIdx.y, tj = blockIdx.x;
    const int t  = ti * NT + tj;
    const int i0 = ti * TPX, j0 = tj * TPX;

    __shared__ float hx[MAXH], hy[MAXH], hc[MAXH];
    __shared__ int scnt;
    const int tid = threadIdx.x;
    if (tid == 0) scnt = g_cnt[t];
    __syncthreads();
    const int cnt = scnt;
    if (tid < cnt) {
        int hi = g_list[t][tid];
        float s = holes[3 * hi + 2];
        hx[tid] = holes[3 * hi];
        hy[tid] = holes[3 * hi + 1];
        hc[tid] = -LOG2E / (2.f * s * s);    // ex2 arg scale
    }
    __syncthreads();

    // thread -> 4 consecutive j (fast dim of out) x 4 strided i rows
    const int jg = (tid & 15) * 4;
    const int ig = tid >> 4;

    float xv[4], yv[4];
    #pragma unroll
    for (int ii = 0; ii < 4; ++ii) xv[ii] = -10.f + 0.005f * (float)(i0 + ig + 16 * ii);
    #pragma unroll
    for (int jj = 0; jj < 4; ++jj) yv[jj] = -10.f + 0.005f * (float)(j0 + jg + jj);

    float acc[4][4];
    #pragma unroll
    for (int ii = 0; ii < 4; ++ii)
        #pragma unroll
        for (int jj = 0; jj < 4; ++jj) acc[ii][jj] = 0.f;

    for (int h = 0; h < cnt; ++h) {
        const float cx = hx[h], cy = hy[h], c = hc[h];
        float ax[4], ay[4];
        #pragma unroll
        for (int ii = 0; ii < 4; ++ii) { float d = xv[ii] - cx; ax[ii] = d * d * c; }
        #pragma unroll
        for (int jj = 0; jj < 4; ++jj) { float d = yv[jj] - cy; ay[jj] = d * d * c; }
        #pragma unroll
        for (int ii = 0; ii < 4; ++ii)
            #pragma unroll
            for (int jj = 0; jj < 4; ++jj)
                acc[ii][jj] += ex2f(ax[ii] + ay[jj]);   // 2^(c*(dx^2+dy^2)) = exp(-d^2/2s^2)
    }

    // sigmoid((Z-0.5)/T) = 1 / (1 + 2^((0.5-Z)*log2e/T))
    const float k = LOG2E * rcpf(*Tptr);

    #pragma unroll
    for (int ii = 0; ii < 4; ++ii) {
        const int i = i0 + ig + 16 * ii;
        if (i >= GN) continue;
        const size_t rb = (size_t)i * GN;
        #pragma unroll
        for (int jj = 0; jj < 4; ++jj) {
            const int j = j0 + jg + jj;
            if (j >= GN) continue;
            float e = ex2f((0.5f - acc[ii][jj]) * k);
            out[rb + j] = rcpf(1.f + e);
        }
    }
}

extern "C" void kernel_launch(void* const* d_in, const int* in_sizes, int n_in,
                              void* d_out, int out_size) {
    const float* holes = (const float*)d_in[0];   // 192 x (x0, y0, sigma)
    const float* Tptr  = (const float*)d_in[1];
    float* out = (float*)d_out;                   // 4001 x 4001 fp32

    build_lists<<<NT * NT, NHOLES>>>(holes);
    {
        dim3 grid(NT, NT);
        eval_tiles<<<grid, 256>>>(holes, Tptr, out);
    }
}

// round 8
// speedup vs baseline: 3.6345x; 1.0295x over previous
#include <cuda_runtime.h>
#include <cstdint>
#include <cstddef>

// Repara_PhC via sparsity, single fused kernel.
// Each Gaussian (sigma=0.1) dies below ~1e-7 beyond r~0.57 units. Per 64x64-px
// tile, the block builds (in smem, ballot compaction, hole-order preserved ->
// deterministic) the list of holes within rect-distance cutoff, then:
//   cnt==0 (most tiles): write block-constant sigmoid(-0.5/T)  (bitwise equal
//                        to the generic path at Z=0 -- same ex2/rcp sequence)
//   cnt>0:  per-pixel sum of 2^(c*d2) + fused sigmoid via ex2/rcp.

#define GN     4001
#define NT     63          // 63 tiles of 64 px cover 4032 >= 4001
#define TPX    64
#define MAXH   32
#define NHOLES 192
#define LOG2E  1.442695041f

__device__ __forceinline__ float ex2f(float x) {
    float r; asm("ex2.approx.ftz.f32 %0, %1;" : "=f"(r) : "f"(x)); return r;
}
__device__ __forceinline__ float rcpf(float x) {
    float r; asm("rcp.approx.ftz.f32 %0, %1;" : "=f"(r) : "f"(x)); return r;
}

__global__ __launch_bounds__(256) void eval_tiles(const float* __restrict__ holes,
                                                  const float* __restrict__ Tptr,
                                                  float* __restrict__ out) {
    const int ti = blockIdx.y, tj = blockIdx.x;
    const int i0 = ti * TPX, j0 = tj * TPX;
    const int tid = threadIdx.x;

    __shared__ float hx[MAXH], hy[MAXH], hc[MAXH];
    __shared__ int wcnt[6], woff[6], scnt;

    // ---- inline per-tile hole list (tid 0..191 = 6 full warps test one hole each) ----
    bool in = false;
    float cx = 0.f, cy = 0.f, cs = 0.f;
    if (tid < NHOLES) {
        cx = holes[3 * tid];
        cy = holes[3 * tid + 1];
        cs = holes[3 * tid + 2];
        const float xlo = -10.f + 0.005f * (float)i0;
        const float xhi = xlo + 0.005f * (float)(TPX - 1);
        const float ylo = -10.f + 0.005f * (float)j0;
        const float yhi = ylo + 0.005f * (float)(TPX - 1);
        const float dx = fmaxf(fmaxf(xlo - cx, cx - xhi), 0.f);
        const float dy = fmaxf(fmaxf(ylo - cy, cy - yhi), 0.f);
        // keep if exp(-d^2/(2 s^2)) >= ~1e-7
        in = (dx * dx + dy * dy) <= (2.f * cs * cs * 16.2f);
    }
    unsigned m = 0;
    const int w = tid >> 5;
    if (tid < NHOLES) {
        m = __ballot_sync(0xffffffffu, in);
        if ((tid & 31) == 0) wcnt[w] = __popc(m);
    }
    __syncthreads();
    if (tid == 0) {
        int o = 0;
        #pragma unroll
        for (int i = 0; i < 6; ++i) { woff[i] = o; o += wcnt[i]; }
        scnt = o < MAXH ? o : MAXH;
    }
    __syncthreads();
    if (in) {
        int pos = woff[w] + __popc(m & ((1u << (tid & 31)) - 1u));
        if (pos < MAXH) {
            hx[pos] = cx; hy[pos] = cy;
            hc[pos] = -LOG2E / (2.f * cs * cs);
        }
    }
    __syncthreads();
    const int cnt = scnt;

    // thread -> 4 consecutive j (fast dim) x 4 strided i rows
    const int jg = (tid & 15) * 4;
    const int ig = tid >> 4;
    const float k = LOG2E * rcpf(*Tptr);

    if (cnt == 0) {
        // Z = 0 everywhere: out = 1/(1 + 2^(0.5*k)), same op sequence as below.
        const float v = rcpf(1.f + ex2f(0.5f * k));
        #pragma unroll
        for (int ii = 0; ii < 4; ++ii) {
            const int i = i0 + ig + 16 * ii;
            if (i >= GN) continue;
            const uint32_t rb = (uint32_t)i * GN + (uint32_t)(j0 + jg);
            #pragma unroll
            for (int jj = 0; jj < 4; ++jj) {
                if (j0 + jg + jj < GN) out[rb + jj] = v;
            }
        }
        return;
    }

    float xv[4], yv[4];
    #pragma unroll
    for (int ii = 0; ii < 4; ++ii) xv[ii] = -10.f + 0.005f * (float)(i0 + ig + 16 * ii);
    #pragma unroll
    for (int jj = 0; jj < 4; ++jj) yv[jj] = -10.f + 0.005f * (float)(j0 + jg + jj);

    float acc[4][4];
    #pragma unroll
    for (int ii = 0; ii < 4; ++ii)
        #pragma unroll
        for (int jj = 0; jj < 4; ++jj) acc[ii][jj] = 0.f;

    for (int h = 0; h < cnt; ++h) {
        const float hcx = hx[h], hcy = hy[h], c = hc[h];
        float ax[4], ay[4];
        #pragma unroll
        for (int ii = 0; ii < 4; ++ii) { float d = xv[ii] - hcx; ax[ii] = d * d * c; }
        #pragma unroll
        for (int jj = 0; jj < 4; ++jj) { float d = yv[jj] - hcy; ay[jj] = d * d * c; }
        #pragma unroll
        for (int ii = 0; ii < 4; ++ii)
            #pragma unroll
            for (int jj = 0; jj < 4; ++jj)
                acc[ii][jj] += ex2f(ax[ii] + ay[jj]);   // == exp(-d^2/(2 s^2))
    }

    // sigmoid((Z-0.5)/T) = 1/(1 + 2^((0.5-Z)*k))
    #pragma unroll
    for (int ii = 0; ii < 4; ++ii) {
        const int i = i0 + ig + 16 * ii;
        if (i >= GN) continue;
        const uint32_t rb = (uint32_t)i * GN + (uint32_t)(j0 + jg);
        #pragma unroll
        for (int jj = 0; jj < 4; ++jj) {
            if (j0 + jg + jj < GN) {
                float e = ex2f((0.5f - acc[ii][jj]) * k);
                out[rb + jj] = rcpf(1.f + e);
            }
        }
    }
}

extern "C" void kernel_launch(void* const* d_in, const int* in_sizes, int n_in,
                              void* d_out, int out_size) {
    const float* holes = (const float*)d_in[0];   // 192 x (x0, y0, sigma)
    const float* Tptr  = (const float*)d_in[1];
    float* out = (float*)d_out;                   // 4001 x 4001 fp32

    dim3 grid(NT, NT);
    eval_tiles<<<grid, 256>>>(holes, Tptr, out);
}

// round 10
// speedup vs baseline: 5.9850x; 1.6467x over previous
#include <cuda_runtime.h>
#include <cstdint>
#include <cstddef>

// Repara_PhC via sparsity, single fused kernel (R9).
// Per 64x64-px tile the block ballot-compacts the holes within cutoff
// (order preserved -> deterministic sums), then either writes the
// block-constant sigmoid (cnt==0, ~75% of tiles) or evaluates
// sum of separable Gaussians + fused sigmoid.
// R9 changes vs R8:
//  - j mapping is stride-16 (j = j0 + tx + 16*jj): every STG.32 warp
//    instruction writes dense 64B runs -> 4x fewer L1 store wavefronts.
//  - hole loop uses separable ex2: acc += ex2(c*dx^2) * ex2(c*dy^2)
//    (8 MUFU + 16 FMA per hole-thread instead of 16 MUFU).

#define GN     4001
#define NT     63          // 63 tiles of 64 px cover 4032 >= 4001
#define TPX    64
#define MAXH   32
#define NHOLES 192
#define LOG2E  1.442695041f

__device__ __forceinline__ float ex2f(float x) {
    float r; asm("ex2.approx.ftz.f32 %0, %1;" : "=f"(r) : "f"(x)); return r;
}
__device__ __forceinline__ float rcpf(float x) {
    float r; asm("rcp.approx.ftz.f32 %0, %1;" : "=f"(r) : "f"(x)); return r;
}

__global__ __launch_bounds__(256) void eval_tiles(const float* __restrict__ holes,
                                                  const float* __restrict__ Tptr,
                                                  float* __restrict__ out) {
    const int ti = blockIdx.y, tj = blockIdx.x;
    const int i0 = ti * TPX, j0 = tj * TPX;
    const int tid = threadIdx.x;

    __shared__ float hx[MAXH], hy[MAXH], hc[MAXH];
    __shared__ int wcnt[6], woff[6], scnt;

    // ---- per-tile hole list (tid 0..191: one hole each, 6 full warps) ----
    bool in = false;
    float cx = 0.f, cy = 0.f, cs = 0.f;
    if (tid < NHOLES) {
        cx = holes[3 * tid];
        cy = holes[3 * tid + 1];
        cs = holes[3 * tid + 2];
        const float xlo = -10.f + 0.005f * (float)i0;
        const float xhi = xlo + 0.005f * (float)(TPX - 1);
        const float ylo = -10.f + 0.005f * (float)j0;
        const float yhi = ylo + 0.005f * (float)(TPX - 1);
        const float dx = fmaxf(fmaxf(xlo - cx, cx - xhi), 0.f);
        const float dy = fmaxf(fmaxf(ylo - cy, cy - yhi), 0.f);
        in = (dx * dx + dy * dy) <= (2.f * cs * cs * 16.2f);   // exp >= ~1e-7
    }
    unsigned m = 0;
    const int w = tid >> 5;
    if (tid < NHOLES) {
        m = __ballot_sync(0xffffffffu, in);
        if ((tid & 31) == 0) wcnt[w] = __popc(m);
    }
    __syncthreads();
    if (tid == 0) {
        int o = 0;
        #pragma unroll
        for (int i = 0; i < 6; ++i) { woff[i] = o; o += wcnt[i]; }
        scnt = o < MAXH ? o : MAXH;
    }
    __syncthreads();
    if (in) {
        int pos = woff[w] + __popc(m & ((1u << (tid & 31)) - 1u));
        if (pos < MAXH) {
            hx[pos] = cx; hy[pos] = cy;
            hc[pos] = -LOG2E / (2.f * cs * cs);
        }
    }
    __syncthreads();
    const int cnt = scnt;

    // thread -> 4 rows (i = i0+ty+16*ii) x 4 cols (j = j0+tx+16*jj), stride-16:
    // each STG.32 from a warp writes 16 consecutive floats per row -> dense lines.
    const int tx = tid & 15;
    const int ty = tid >> 4;
    const float k = LOG2E * rcpf(*Tptr);

    if (cnt == 0) {
        // Z = 0 everywhere: same op sequence as generic path at acc=0.
        const float v = rcpf(1.f + ex2f(0.5f * k));
        #pragma unroll
        for (int ii = 0; ii < 4; ++ii) {
            const int i = i0 + ty + 16 * ii;
            if (i >= GN) continue;
            const uint32_t rb = (uint32_t)i * GN;
            #pragma unroll
            for (int jj = 0; jj < 4; ++jj) {
                const int j = j0 + tx + 16 * jj;
                if (j < GN) out[rb + j] = v;
            }
        }
        return;
    }

    float xv[4], yv[4];
    #pragma unroll
    for (int ii = 0; ii < 4; ++ii) xv[ii] = -10.f + 0.005f * (float)(i0 + ty + 16 * ii);
    #pragma unroll
    for (int jj = 0; jj < 4; ++jj) yv[jj] = -10.f + 0.005f * (float)(j0 + tx + 16 * jj);

    float acc[4][4];
    #pragma unroll
    for (int ii = 0; ii < 4; ++ii)
        #pragma unroll
        for (int jj = 0; jj < 4; ++jj) acc[ii][jj] = 0.f;

    for (int h = 0; h < cnt; ++h) {
        const float hcx = hx[h], hcy = hy[h], c = hc[h];
        float ex[4], ey[4];
        #pragma unroll
        for (int ii = 0; ii < 4; ++ii) { float d = xv[ii] - hcx; ex[ii] = ex2f(d * d * c); }
        #pragma unroll
        for (int jj = 0; jj < 4; ++jj) { float d = yv[jj] - hcy; ey[jj] = ex2f(d * d * c); }
        #pragma unroll
        for (int ii = 0; ii < 4; ++ii)
            #pragma unroll
            for (int jj = 0; jj < 4; ++jj)
                acc[ii][jj] = fmaf(ex[ii], ey[jj], acc[ii][jj]);  // 2^(c(dx^2+dy^2))
    }

    // sigmoid((Z-0.5)/T) = 1/(1 + 2^((0.5-Z)*k))
    #pragma unroll
    for (int ii = 0; ii < 4; ++ii) {
        const int i = i0 + ty + 16 * ii;
        if (i >= GN) continue;
        const uint32_t rb = (uint32_t)i * GN;
        #pragma unroll
        for (int jj = 0; jj < 4; ++jj) {
            const int j = j0 + tx + 16 * jj;
            if (j < GN) {
                float e = ex2f((0.5f - acc[ii][jj]) * k);
                out[rb + j] = rcpf(1.f + e);
            }
        }
    }
}

extern "C" void kernel_launch(void* const* d_in, const int* in_sizes, int n_in,
                              void* d_out, int out_size) {
    const float* holes = (const float*)d_in[0];   // 192 x (x0, y0, sigma)
    const float* Tptr  = (const float*)d_in[1];
    float* out = (float*)d_out;                   // 4001 x 4001 fp32

    dim3 grid(NT, NT);
    eval_tiles<<<grid, 256>>>(holes, Tptr, out);
}